// round 8
// baseline (speedup 1.0000x reference)
#include <cuda_runtime.h>
#include <math.h>
#include <stdint.h>

#define TAU 5e-5f
#define MAXFLAG 8192

__device__ int   g_hist[32];
__device__ int   g_nflag;
__device__ int   g_flag[MAXFLAG];

__device__ __forceinline__ float tf32r(float x) {
    float r; asm("cvt.rna.tf32.f32 %0, %1;" : "=f"(r) : "f"(x)); return r;
}

#define MMA8(c, a, b0_, b1_) \
    asm volatile("mma.sync.aligned.m16n8k8.row.col.f32.tf32.tf32.f32 " \
        "{%0,%1,%2,%3}, {%4,%5,%6,%7}, {%8,%9}, {%0,%1,%2,%3};" \
        : "+f"((c)[0]), "+f"((c)[1]), "+f"((c)[2]), "+f"((c)[3]) \
        : "r"((a)[0]), "r"((a)[1]), "r"((a)[2]), "r"((a)[3]), "r"(b0_), "r"(b1_))

__global__ void init_kernel() {
    if (threadIdx.x < 32) g_hist[threadIdx.x] = 0;
    if (threadIdx.x == 0) g_nflag = 0;
}

// smem float layout:
//   [0,128)   bias (b0+b1)
//   [128,..)  2 buffers, stride 8704 floats each:
//             A_h @ +0 (16x136), A_l @ +2176, B_h @ +4352, B_l @ +6528
//   epilogue: xs (128 x 132) reuses [128,..)
#define SBUF 8704
#define PAD  136

__device__ __forceinline__ void ldg_tile(float4 va[2], float4 vb[2], int t, int m0, int tid,
                                         const float* __restrict__ s0g,
                                         const float* __restrict__ s1g,
                                         const float* __restrict__ W0g,
                                         const float* __restrict__ W1g) {
    const int phase = t >> 8, kt = t & 255;
    const float* Ag = phase ? s1g : s0g;
    const float* Wg = phase ? W1g : W0g;
#pragma unroll
    for (int i = 0; i < 2; ++i) {
        const int f = i * 256 + tid;
        const int arow = f & 127, aq = f >> 7;          // A: row, quad(k/4)
        va[i] = *(const float4*)(Ag + (size_t)(m0 + arow) * 4096 + kt * 16 + aq * 4);
        const int bk = f >> 5, bnq = f & 31;            // B: k row, n quad
        vb[i] = *(const float4*)(Wg + (size_t)(kt * 16 + bk) * 128 + bnq * 4);
    }
}

__device__ __forceinline__ void sts_tile(float* __restrict__ buf, const float4 va[2],
                                         const float4 vb[2], int tid) {
#pragma unroll
    for (int i = 0; i < 2; ++i) {
        const int f = i * 256 + tid;
        const int arow = f & 127, aq = f >> 7;
        const float ax[4] = {va[i].x, va[i].y, va[i].z, va[i].w};
#pragma unroll
        for (int j = 0; j < 4; ++j) {
            const float h = tf32r(ax[j]);
            const int k = aq * 4 + j;
            buf[k * PAD + arow]        = h;
            buf[2176 + k * PAD + arow] = tf32r(ax[j] - h);
        }
        const int bk = f >> 5, bnq = f & 31;
        float4 wh, wl;
        wh.x = tf32r(vb[i].x); wl.x = tf32r(vb[i].x - wh.x);
        wh.y = tf32r(vb[i].y); wl.y = tf32r(vb[i].y - wh.y);
        wh.z = tf32r(vb[i].z); wl.z = tf32r(vb[i].z - wh.z);
        wh.w = tf32r(vb[i].w); wl.w = tf32r(vb[i].w - wh.w);
        *(float4*)(buf + 4352 + bk * PAD + bnq * 4) = wh;
        *(float4*)(buf + 6528 + bk * PAD + bnq * 4) = wl;
    }
}

__device__ __forceinline__ void compute_tile(const float* __restrict__ buf,
                                             float c[2][8][4],
                                             int wm, int wn, int g, int tig) {
    const float* Ah = buf;
    const float* Al = buf + 2176;
    const float* Bh = buf + 4352;
    const float* Bl = buf + 6528;
#pragma unroll
    for (int k8 = 0; k8 < 2; ++k8) {
        const int kr = k8 * 8 + tig;
        uint32_t a[2][2][4];
#pragma unroll
        for (int mt = 0; mt < 2; ++mt) {
            const int mb = wm * 32 + mt * 16 + g;
            a[mt][0][0] = __float_as_uint(Ah[kr * PAD + mb]);
            a[mt][0][1] = __float_as_uint(Ah[kr * PAD + mb + 8]);
            a[mt][0][2] = __float_as_uint(Ah[(kr + 4) * PAD + mb]);
            a[mt][0][3] = __float_as_uint(Ah[(kr + 4) * PAD + mb + 8]);
            a[mt][1][0] = __float_as_uint(Al[kr * PAD + mb]);
            a[mt][1][1] = __float_as_uint(Al[kr * PAD + mb + 8]);
            a[mt][1][2] = __float_as_uint(Al[(kr + 4) * PAD + mb]);
            a[mt][1][3] = __float_as_uint(Al[(kr + 4) * PAD + mb + 8]);
        }
#pragma unroll
        for (int nt = 0; nt < 8; ++nt) {
            const int nb = wn * 64 + nt * 8 + g;
            const uint32_t bh0 = __float_as_uint(Bh[kr * PAD + nb]);
            const uint32_t bh1 = __float_as_uint(Bh[(kr + 4) * PAD + nb]);
            const uint32_t bl0 = __float_as_uint(Bl[kr * PAD + nb]);
            const uint32_t bl1 = __float_as_uint(Bl[(kr + 4) * PAD + nb]);
#pragma unroll
            for (int mt = 0; mt < 2; ++mt) {
                MMA8(c[mt][nt], a[mt][0], bh0, bh1);   // hi*hi
                MMA8(c[mt][nt], a[mt][0], bl0, bl1);   // hi*lo
                MMA8(c[mt][nt], a[mt][1], bh0, bh1);   // lo*hi
            }
        }
    }
}

__global__ __launch_bounds__(256, 2)
void gemm_vq_mma(const float* __restrict__ s0g, const float* __restrict__ s1g,
                 const float* __restrict__ W0g, const float* __restrict__ b0g,
                 const float* __restrict__ W1g, const float* __restrict__ b1g,
                 const float* __restrict__ Wfg, const float* __restrict__ bfg,
                 const float* __restrict__ cbg, float* __restrict__ out,
                 int N, int Kcb)
{
    extern __shared__ float sm[];
    const int tid  = threadIdx.x;
    const int lane = tid & 31, wid = tid >> 5;
    const int g = lane >> 2, tig = lane & 3;
    const int wm = wid & 3, wn = wid >> 2;
    const int m0 = blockIdx.x * 128;

    if (tid < 128) sm[tid] = b0g[tid] + b1g[tid];

    float c[2][8][4];
#pragma unroll
    for (int mt = 0; mt < 2; ++mt)
#pragma unroll
        for (int nt = 0; nt < 8; ++nt)
#pragma unroll
            for (int r = 0; r < 4; ++r) c[mt][nt][r] = 0.0f;

    float* buf0 = sm + 128;
    float* buf1 = sm + 128 + SBUF;

    float4 va[2], vb[2];
    ldg_tile(va, vb, 0, m0, tid, s0g, s1g, W0g, W1g);
    sts_tile(buf0, va, vb, tid);
    __syncthreads();

    for (int t = 0; t < 512; ++t) {
        if (t + 1 < 512) ldg_tile(va, vb, t + 1, m0, tid, s0g, s1g, W0g, W1g);
        compute_tile((t & 1) ? buf1 : buf0, c, wm, wn, g, tig);
        if (t + 1 < 512) sts_tile((t & 1) ? buf0 : buf1, va, vb, tid);
        __syncthreads();
    }

    // ---- epilogue: relu(acc + bias) -> xs smem (row pad 132) ----
    float* xs = sm + 128;
#pragma unroll
    for (int mt = 0; mt < 2; ++mt)
#pragma unroll
        for (int nt = 0; nt < 8; ++nt) {
            const int col = wn * 64 + nt * 8 + tig * 2;
            const float bv0 = sm[col], bv1 = sm[col + 1];
            const int r0 = wm * 32 + mt * 16 + g;
            float2 v0, v1;
            v0.x = fmaxf(c[mt][nt][0] + bv0, 0.0f);
            v0.y = fmaxf(c[mt][nt][1] + bv1, 0.0f);
            v1.x = fmaxf(c[mt][nt][2] + bv0, 0.0f);
            v1.y = fmaxf(c[mt][nt][3] + bv1, 0.0f);
            *(float2*)(xs + r0 * 132 + col)       = v0;
            *(float2*)(xs + (r0 + 8) * 132 + col) = v1;
        }
    __syncthreads();

    // ---- per-row: fp64 flat, reference distance expansion, margin-checked argmin ----
    if (tid < 128) {
        const float* xr = xs + tid * 132;
        double F0 = 0.0, F1 = 0.0, F2 = 0.0, F3 = 0.0;
#pragma unroll 8
        for (int h = 0; h < 128; ++h) {
            const double xv = (double)xr[h];
            F0 = fma(xv, (double)__ldg(Wfg + h * 4 + 0), F0);
            F1 = fma(xv, (double)__ldg(Wfg + h * 4 + 1), F1);
            F2 = fma(xv, (double)__ldg(Wfg + h * 4 + 2), F2);
            F3 = fma(xv, (double)__ldg(Wfg + h * 4 + 3), F3);
        }
        const float f0 = (float)(F0 + (double)__ldg(bfg + 0));
        const float f1 = (float)(F1 + (double)__ldg(bfg + 1));
        const float f2 = (float)(F2 + (double)__ldg(bfg + 2));
        const float f3 = (float)(F3 + (double)__ldg(bfg + 3));

        const float ff = ((f0 * f0 + f1 * f1) + f2 * f2) + f3 * f3;
        float dmin = 3.4e38f, dsec = 3.4e38f;
        int best = 0;
        for (int k = 0; k < Kcb; ++k) {
            const float c0 = __ldg(cbg + k * 4 + 0), c1 = __ldg(cbg + k * 4 + 1);
            const float c2 = __ldg(cbg + k * 4 + 2), c3 = __ldg(cbg + k * 4 + 3);
            const float cc  = ((c0 * c0 + c1 * c1) + c2 * c2) + c3 * c3;
            const float dot = ((f0 * c0 + f1 * c1) + f2 * c2) + f3 * c3;
            const float tt  = ff + cc;
            const float dk  = tt - 2.0f * dot;
            if (dk < dmin) { dsec = dmin; dmin = dk; best = k; }
            else if (dk < dsec) { dsec = dk; }
        }
        const int gr = m0 + tid;
        if (dsec - dmin < TAU) {
            // near-tie: defer this row to the bit-exact repair pass
            const int s = atomicAdd(&g_nflag, 1);
            if (s < MAXFLAG) g_flag[s] = gr;
        } else {
            const float c0 = __ldg(cbg + best * 4 + 0), c1 = __ldg(cbg + best * 4 + 1);
            const float c2 = __ldg(cbg + best * 4 + 2), c3 = __ldg(cbg + best * 4 + 3);
            const size_t zbase = (size_t)gr * 4;
            out[zbase + 0] = f0 + (c0 - f0);
            out[zbase + 1] = f1 + (c1 - f1);
            out[zbase + 2] = f2 + (c2 - f2);
            out[zbase + 3] = f3 + (c3 - f3);
            const float d0 = c0 - f0, d1 = c1 - f1, d2 = c2 - f2, d3 = c3 - f3;
            float m = ((d0 * d0 + d1 * d1) + d2 * d2) + d3 * d3;
            m *= 0.25f;
            const size_t zlen = (size_t)N * 4;
            out[zlen + gr] = m + m;
            out[zlen + (size_t)N + 1 + gr] = (float)best;
            atomicAdd(&g_hist[best], 1);
        }
    }
}

// ---- repair: recompute flagged rows with the exact R2 arithmetic (serial fp32
//      FFMA chain, k ascending, phase0 then phase1, bias (b0+b1) added once) ----
__global__ __launch_bounds__(128, 8)
void repair_kernel(const float* __restrict__ s0g, const float* __restrict__ s1g,
                   const float* __restrict__ W0g, const float* __restrict__ b0g,
                   const float* __restrict__ W1g, const float* __restrict__ b1g,
                   const float* __restrict__ Wfg, const float* __restrict__ bfg,
                   const float* __restrict__ cbg, float* __restrict__ out,
                   int N, int Kcb)
{
    const int nf = min(g_nflag, MAXFLAG);
    const int b  = blockIdx.x;
    if (b >= nf) return;
    const int r = g_flag[b];

    __shared__ float xsr[128];
    const int h = threadIdx.x;
    float acc = 0.0f;
    const float* a0 = s0g + (size_t)r * 4096;
#pragma unroll 4
    for (int k = 0; k < 4096; ++k) acc = fmaf(a0[k], __ldg(W0g + (size_t)k * 128 + h), acc);
    const float* a1 = s1g + (size_t)r * 4096;
#pragma unroll 4
    for (int k = 0; k < 4096; ++k) acc = fmaf(a1[k], __ldg(W1g + (size_t)k * 128 + h), acc);
    xsr[h] = fmaxf(acc + (__ldg(b0g + h) + __ldg(b1g + h)), 0.0f);
    __syncthreads();

    if (h == 0) {
        double F0 = 0.0, F1 = 0.0, F2 = 0.0, F3 = 0.0;
        for (int j = 0; j < 128; ++j) {
            const double xv = (double)xsr[j];
            F0 = fma(xv, (double)__ldg(Wfg + j * 4 + 0), F0);
            F1 = fma(xv, (double)__ldg(Wfg + j * 4 + 1), F1);
            F2 = fma(xv, (double)__ldg(Wfg + j * 4 + 2), F2);
            F3 = fma(xv, (double)__ldg(Wfg + j * 4 + 3), F3);
        }
        const float f0 = (float)(F0 + (double)__ldg(bfg + 0));
        const float f1 = (float)(F1 + (double)__ldg(bfg + 1));
        const float f2 = (float)(F2 + (double)__ldg(bfg + 2));
        const float f3 = (float)(F3 + (double)__ldg(bfg + 3));

        const float ff = ((f0 * f0 + f1 * f1) + f2 * f2) + f3 * f3;
        float dmin = 3.4e38f;
        int best = 0;
        for (int k = 0; k < Kcb; ++k) {
            const float c0 = __ldg(cbg + k * 4 + 0), c1 = __ldg(cbg + k * 4 + 1);
            const float c2 = __ldg(cbg + k * 4 + 2), c3 = __ldg(cbg + k * 4 + 3);
            const float cc  = ((c0 * c0 + c1 * c1) + c2 * c2) + c3 * c3;
            const float dot = ((f0 * c0 + f1 * c1) + f2 * c2) + f3 * c3;
            const float tt  = ff + cc;
            const float dk  = tt - 2.0f * dot;
            if (dk < dmin) { dmin = dk; best = k; }
        }
        const float c0 = __ldg(cbg + best * 4 + 0), c1 = __ldg(cbg + best * 4 + 1);
        const float c2 = __ldg(cbg + best * 4 + 2), c3 = __ldg(cbg + best * 4 + 3);
        const size_t zbase = (size_t)r * 4;
        out[zbase + 0] = f0 + (c0 - f0);
        out[zbase + 1] = f1 + (c1 - f1);
        out[zbase + 2] = f2 + (c2 - f2);
        out[zbase + 3] = f3 + (c3 - f3);
        const float d0 = c0 - f0, d1 = c1 - f1, d2 = c2 - f2, d3 = c3 - f3;
        float m = ((d0 * d0 + d1 * d1) + d2 * d2) + d3 * d3;
        m *= 0.25f;
        const size_t zlen = (size_t)N * 4;
        out[zlen + r] = m + m;
        out[zlen + (size_t)N + 1 + r] = (float)best;
        atomicAdd(&g_hist[best], 1);
    }
}

__global__ void finalize_kernel(float* __restrict__ out, int N, int K) {
    if (threadIdx.x == 0) {
        const float invN = 1.0f / (float)N;
        float s = 0.0f;
        for (int k = 0; k < K; ++k) {
            const float p = (float)g_hist[k] * invN;
            s += p * logf(p + 1e-10f);
        }
        out[(size_t)N * 4 + N] = expf(-s);  // perplexity
    }
}

extern "C" void kernel_launch(void* const* d_in, const int* in_sizes, int n_in,
                              void* d_out, int out_size) {
    const float* s0 = (const float*)d_in[0];
    const float* s1 = (const float*)d_in[1];
    const float* W0 = (const float*)d_in[2];
    const float* b0 = (const float*)d_in[3];
    const float* W1 = (const float*)d_in[4];
    const float* b1 = (const float*)d_in[5];
    const float* Wf = (const float*)d_in[6];
    const float* bf = (const float*)d_in[7];
    const float* cb = (const float*)d_in[8];
    float* out = (float*)d_out;

    const int H = in_sizes[3];         // 128
    const int E = in_sizes[7];         // 4
    const int K = in_sizes[8] / E;     // 30
    const int D = in_sizes[2] / H;     // 4096
    const int N = in_sizes[0] / D;     // 32768

    const int smem_bytes = (128 + 2 * SBUF) * (int)sizeof(float);  // 70144
    cudaFuncSetAttribute(gemm_vq_mma,
                         cudaFuncAttributeMaxDynamicSharedMemorySize, smem_bytes);

    init_kernel<<<1, 32>>>();
    gemm_vq_mma<<<N / 128, 256, smem_bytes>>>(s0, s1, W0, b0, W1, b1,
                                              Wf, bf, cb, out, N, K);
    repair_kernel<<<MAXFLAG, 128>>>(s0, s1, W0, b0, W1, b1, Wf, bf, cb, out, N, K);
    finalize_kernel<<<1, 32>>>(out, N, K);
}

// round 9
// speedup vs baseline: 1.0002x; 1.0002x over previous
#include <cuda_runtime.h>
#include <math.h>
#include <stdint.h>

#define TAU 5e-5f
#define MAXFLAG 8192

__device__ int   g_hist[32];
__device__ int   g_nflag;
__device__ int   g_flag[MAXFLAG];

__device__ __forceinline__ float tf32r(float x) {
    float r; asm("cvt.rna.tf32.f32 %0, %1;" : "=f"(r) : "f"(x)); return r;
}

#define MMA8(c, a, b0_, b1_) \
    asm volatile("mma.sync.aligned.m16n8k8.row.col.f32.tf32.tf32.f32 " \
        "{%0,%1,%2,%3}, {%4,%5,%6,%7}, {%8,%9}, {%0,%1,%2,%3};" \
        : "+f"((c)[0]), "+f"((c)[1]), "+f"((c)[2]), "+f"((c)[3]) \
        : "r"((a)[0]), "r"((a)[1]), "r"((a)[2]), "r"((a)[3]), "r"(b0_), "r"(b1_))

__global__ void init_kernel() {
    if (threadIdx.x < 32) g_hist[threadIdx.x] = 0;
    if (threadIdx.x == 0) g_nflag = 0;
}

// smem float layout:
//   [0,128)   bias (b0+b1)
//   [128,..)  2 buffers, stride 8704 floats each:
//             A_h @ +0 (16x136), A_l @ +2176, B_h @ +4352, B_l @ +6528
//   epilogue: xs (128 x 132) reuses [128,..)
#define SBUF 8704
#define PAD  136

__device__ __forceinline__ void ldg_tile(float4 va[2], float4 vb[2], int t, int m0, int tid,
                                         const float* __restrict__ s0g,
                                         const float* __restrict__ s1g,
                                         const float* __restrict__ W0g,
                                         const float* __restrict__ W1g) {
    const int phase = t >> 8, kt = t & 255;
    const float* Ag = phase ? s1g : s0g;
    const float* Wg = phase ? W1g : W0g;
#pragma unroll
    for (int i = 0; i < 2; ++i) {
        const int f = i * 256 + tid;
        const int arow = f & 127, aq = f >> 7;          // A: row, quad(k/4)
        va[i] = *(const float4*)(Ag + (size_t)(m0 + arow) * 4096 + kt * 16 + aq * 4);
        const int bk = f >> 5, bnq = f & 31;            // B: k row, n quad
        vb[i] = *(const float4*)(Wg + (size_t)(kt * 16 + bk) * 128 + bnq * 4);
    }
}

__device__ __forceinline__ void sts_tile(float* __restrict__ buf, const float4 va[2],
                                         const float4 vb[2], int tid) {
#pragma unroll
    for (int i = 0; i < 2; ++i) {
        const int f = i * 256 + tid;
        const int arow = f & 127, aq = f >> 7;
        const float ax[4] = {va[i].x, va[i].y, va[i].z, va[i].w};
#pragma unroll
        for (int j = 0; j < 4; ++j) {
            const float h = tf32r(ax[j]);
            const int k = aq * 4 + j;
            buf[k * PAD + arow]        = h;
            buf[2176 + k * PAD + arow] = tf32r(ax[j] - h);
        }
        const int bk = f >> 5, bnq = f & 31;
        float4 wh, wl;
        wh.x = tf32r(vb[i].x); wl.x = tf32r(vb[i].x - wh.x);
        wh.y = tf32r(vb[i].y); wl.y = tf32r(vb[i].y - wh.y);
        wh.z = tf32r(vb[i].z); wl.z = tf32r(vb[i].z - wh.z);
        wh.w = tf32r(vb[i].w); wl.w = tf32r(vb[i].w - wh.w);
        *(float4*)(buf + 4352 + bk * PAD + bnq * 4) = wh;
        *(float4*)(buf + 6528 + bk * PAD + bnq * 4) = wl;
    }
}

__device__ __forceinline__ void compute_tile(const float* __restrict__ buf,
                                             float c[2][8][4],
                                             int wm, int wn, int g, int tig) {
    const float* Ah = buf;
    const float* Al = buf + 2176;
    const float* Bh = buf + 4352;
    const float* Bl = buf + 6528;
#pragma unroll
    for (int k8 = 0; k8 < 2; ++k8) {
        const int kr = k8 * 8 + tig;
        uint32_t a[2][2][4];
#pragma unroll
        for (int mt = 0; mt < 2; ++mt) {
            const int mb = wm * 32 + mt * 16 + g;
            a[mt][0][0] = __float_as_uint(Ah[kr * PAD + mb]);
            a[mt][0][1] = __float_as_uint(Ah[kr * PAD + mb + 8]);
            a[mt][0][2] = __float_as_uint(Ah[(kr + 4) * PAD + mb]);
            a[mt][0][3] = __float_as_uint(Ah[(kr + 4) * PAD + mb + 8]);
            a[mt][1][0] = __float_as_uint(Al[kr * PAD + mb]);
            a[mt][1][1] = __float_as_uint(Al[kr * PAD + mb + 8]);
            a[mt][1][2] = __float_as_uint(Al[(kr + 4) * PAD + mb]);
            a[mt][1][3] = __float_as_uint(Al[(kr + 4) * PAD + mb + 8]);
        }
#pragma unroll
        for (int nt = 0; nt < 8; ++nt) {
            const int nb = wn * 64 + nt * 8 + g;
            const uint32_t bh0 = __float_as_uint(Bh[kr * PAD + nb]);
            const uint32_t bh1 = __float_as_uint(Bh[(kr + 4) * PAD + nb]);
            const uint32_t bl0 = __float_as_uint(Bl[kr * PAD + nb]);
            const uint32_t bl1 = __float_as_uint(Bl[(kr + 4) * PAD + nb]);
#pragma unroll
            for (int mt = 0; mt < 2; ++mt) {
                MMA8(c[mt][nt], a[mt][0], bh0, bh1);   // hi*hi
                MMA8(c[mt][nt], a[mt][0], bl0, bl1);   // hi*lo
                MMA8(c[mt][nt], a[mt][1], bh0, bh1);   // lo*hi
            }
        }
    }
}

__global__ __launch_bounds__(256, 2)
void gemm_vq_mma(const float* __restrict__ s0g, const float* __restrict__ s1g,
                 const float* __restrict__ W0g, const float* __restrict__ b0g,
                 const float* __restrict__ W1g, const float* __restrict__ b1g,
                 const float* __restrict__ Wfg, const float* __restrict__ bfg,
                 const float* __restrict__ cbg, float* __restrict__ out,
                 int N, int Kcb)
{
    extern __shared__ float sm[];
    const int tid  = threadIdx.x;
    const int lane = tid & 31, wid = tid >> 5;
    const int g = lane >> 2, tig = lane & 3;
    const int wm = wid & 3, wn = wid >> 2;
    const int m0 = blockIdx.x * 128;

    if (tid < 128) sm[tid] = b0g[tid] + b1g[tid];

    float c[2][8][4];
#pragma unroll
    for (int mt = 0; mt < 2; ++mt)
#pragma unroll
        for (int nt = 0; nt < 8; ++nt)
#pragma unroll
            for (int r = 0; r < 4; ++r) c[mt][nt][r] = 0.0f;

    float* buf0 = sm + 128;
    float* buf1 = sm + 128 + SBUF;

    float4 va[2], vb[2];
    ldg_tile(va, vb, 0, m0, tid, s0g, s1g, W0g, W1g);
    sts_tile(buf0, va, vb, tid);
    __syncthreads();

    for (int t = 0; t < 512; ++t) {
        if (t + 1 < 512) ldg_tile(va, vb, t + 1, m0, tid, s0g, s1g, W0g, W1g);
        compute_tile((t & 1) ? buf1 : buf0, c, wm, wn, g, tig);
        if (t + 1 < 512) sts_tile((t & 1) ? buf0 : buf1, va, vb, tid);
        __syncthreads();
    }

    // ---- epilogue: relu(acc + bias) -> xs smem (row pad 132) ----
    float* xs = sm + 128;
#pragma unroll
    for (int mt = 0; mt < 2; ++mt)
#pragma unroll
        for (int nt = 0; nt < 8; ++nt) {
            const int col = wn * 64 + nt * 8 + tig * 2;
            const float bv0 = sm[col], bv1 = sm[col + 1];
            const int r0 = wm * 32 + mt * 16 + g;
            float2 v0, v1;
            v0.x = fmaxf(c[mt][nt][0] + bv0, 0.0f);
            v0.y = fmaxf(c[mt][nt][1] + bv1, 0.0f);
            v1.x = fmaxf(c[mt][nt][2] + bv0, 0.0f);
            v1.y = fmaxf(c[mt][nt][3] + bv1, 0.0f);
            *(float2*)(xs + r0 * 132 + col)       = v0;
            *(float2*)(xs + (r0 + 8) * 132 + col) = v1;
        }
    __syncthreads();

    // ---- per-row: fp64 flat, reference distance expansion, margin-checked argmin ----
    if (tid < 128) {
        const float* xr = xs + tid * 132;
        double F0 = 0.0, F1 = 0.0, F2 = 0.0, F3 = 0.0;
#pragma unroll 8
        for (int h = 0; h < 128; ++h) {
            const double xv = (double)xr[h];
            F0 = fma(xv, (double)__ldg(Wfg + h * 4 + 0), F0);
            F1 = fma(xv, (double)__ldg(Wfg + h * 4 + 1), F1);
            F2 = fma(xv, (double)__ldg(Wfg + h * 4 + 2), F2);
            F3 = fma(xv, (double)__ldg(Wfg + h * 4 + 3), F3);
        }
        const float f0 = (float)(F0 + (double)__ldg(bfg + 0));
        const float f1 = (float)(F1 + (double)__ldg(bfg + 1));
        const float f2 = (float)(F2 + (double)__ldg(bfg + 2));
        const float f3 = (float)(F3 + (double)__ldg(bfg + 3));

        const float ff = ((f0 * f0 + f1 * f1) + f2 * f2) + f3 * f3;
        float dmin = 3.4e38f, dsec = 3.4e38f;
        int best = 0;
        for (int k = 0; k < Kcb; ++k) {
            const float c0 = __ldg(cbg + k * 4 + 0), c1 = __ldg(cbg + k * 4 + 1);
            const float c2 = __ldg(cbg + k * 4 + 2), c3 = __ldg(cbg + k * 4 + 3);
            const float cc  = ((c0 * c0 + c1 * c1) + c2 * c2) + c3 * c3;
            const float dot = ((f0 * c0 + f1 * c1) + f2 * c2) + f3 * c3;
            const float tt  = ff + cc;
            const float dk  = tt - 2.0f * dot;
            if (dk < dmin) { dsec = dmin; dmin = dk; best = k; }
            else if (dk < dsec) { dsec = dk; }
        }
        const int gr = m0 + tid;
        if (dsec - dmin < TAU) {
            // near-tie: defer this row to the bit-exact repair pass
            const int s = atomicAdd(&g_nflag, 1);
            if (s < MAXFLAG) g_flag[s] = gr;
        } else {
            const float c0 = __ldg(cbg + best * 4 + 0), c1 = __ldg(cbg + best * 4 + 1);
            const float c2 = __ldg(cbg + best * 4 + 2), c3 = __ldg(cbg + best * 4 + 3);
            const size_t zbase = (size_t)gr * 4;
            out[zbase + 0] = f0 + (c0 - f0);
            out[zbase + 1] = f1 + (c1 - f1);
            out[zbase + 2] = f2 + (c2 - f2);
            out[zbase + 3] = f3 + (c3 - f3);
            const float d0 = c0 - f0, d1 = c1 - f1, d2 = c2 - f2, d3 = c3 - f3;
            float m = ((d0 * d0 + d1 * d1) + d2 * d2) + d3 * d3;
            m *= 0.25f;
            const size_t zlen = (size_t)N * 4;
            out[zlen + gr] = m + m;
            out[zlen + (size_t)N + 1 + gr] = (float)best;
            atomicAdd(&g_hist[best], 1);
        }
    }
}

// ---- repair: recompute flagged rows with the exact R2 arithmetic (serial fp32
//      FFMA chain, k ascending, phase0 then phase1, bias (b0+b1) added once) ----
__global__ __launch_bounds__(128, 8)
void repair_kernel(const float* __restrict__ s0g, const float* __restrict__ s1g,
                   const float* __restrict__ W0g, const float* __restrict__ b0g,
                   const float* __restrict__ W1g, const float* __restrict__ b1g,
                   const float* __restrict__ Wfg, const float* __restrict__ bfg,
                   const float* __restrict__ cbg, float* __restrict__ out,
                   int N, int Kcb)
{
    const int nf = min(g_nflag, MAXFLAG);
    const int b  = blockIdx.x;
    if (b >= nf) return;
    const int r = g_flag[b];

    __shared__ float xsr[128];
    const int h = threadIdx.x;
    float acc = 0.0f;
    const float* a0 = s0g + (size_t)r * 4096;
#pragma unroll 4
    for (int k = 0; k < 4096; ++k) acc = fmaf(a0[k], __ldg(W0g + (size_t)k * 128 + h), acc);
    const float* a1 = s1g + (size_t)r * 4096;
#pragma unroll 4
    for (int k = 0; k < 4096; ++k) acc = fmaf(a1[k], __ldg(W1g + (size_t)k * 128 + h), acc);
    xsr[h] = fmaxf(acc + (__ldg(b0g + h) + __ldg(b1g + h)), 0.0f);
    __syncthreads();

    if (h == 0) {
        double F0 = 0.0, F1 = 0.0, F2 = 0.0, F3 = 0.0;
        for (int j = 0; j < 128; ++j) {
            const double xv = (double)xsr[j];
            F0 = fma(xv, (double)__ldg(Wfg + j * 4 + 0), F0);
            F1 = fma(xv, (double)__ldg(Wfg + j * 4 + 1), F1);
            F2 = fma(xv, (double)__ldg(Wfg + j * 4 + 2), F2);
            F3 = fma(xv, (double)__ldg(Wfg + j * 4 + 3), F3);
        }
        const float f0 = (float)(F0 + (double)__ldg(bfg + 0));
        const float f1 = (float)(F1 + (double)__ldg(bfg + 1));
        const float f2 = (float)(F2 + (double)__ldg(bfg + 2));
        const float f3 = (float)(F3 + (double)__ldg(bfg + 3));

        const float ff = ((f0 * f0 + f1 * f1) + f2 * f2) + f3 * f3;
        float dmin = 3.4e38f;
        int best = 0;
        for (int k = 0; k < Kcb; ++k) {
            const float c0 = __ldg(cbg + k * 4 + 0), c1 = __ldg(cbg + k * 4 + 1);
            const float c2 = __ldg(cbg + k * 4 + 2), c3 = __ldg(cbg + k * 4 + 3);
            const float cc  = ((c0 * c0 + c1 * c1) + c2 * c2) + c3 * c3;
            const float dot = ((f0 * c0 + f1 * c1) + f2 * c2) + f3 * c3;
            const float tt  = ff + cc;
            const float dk  = tt - 2.0f * dot;
            if (dk < dmin) { dmin = dk; best = k; }
        }
        const float c0 = __ldg(cbg + best * 4 + 0), c1 = __ldg(cbg + best * 4 + 1);
        const float c2 = __ldg(cbg + best * 4 + 2), c3 = __ldg(cbg + best * 4 + 3);
        const size_t zbase = (size_t)r * 4;
        out[zbase + 0] = f0 + (c0 - f0);
        out[zbase + 1] = f1 + (c1 - f1);
        out[zbase + 2] = f2 + (c2 - f2);
        out[zbase + 3] = f3 + (c3 - f3);
        const float d0 = c0 - f0, d1 = c1 - f1, d2 = c2 - f2, d3 = c3 - f3;
        float m = ((d0 * d0 + d1 * d1) + d2 * d2) + d3 * d3;
        m *= 0.25f;
        const size_t zlen = (size_t)N * 4;
        out[zlen + r] = m + m;
        out[zlen + (size_t)N + 1 + r] = (float)best;
        atomicAdd(&g_hist[best], 1);
    }
}

__global__ void finalize_kernel(float* __restrict__ out, int N, int K) {
    if (threadIdx.x == 0) {
        const float invN = 1.0f / (float)N;
        float s = 0.0f;
        for (int k = 0; k < K; ++k) {
            const float p = (float)g_hist[k] * invN;
            s += p * logf(p + 1e-10f);
        }
        out[(size_t)N * 4 + N] = expf(-s);  // perplexity
    }
}

extern "C" void kernel_launch(void* const* d_in, const int* in_sizes, int n_in,
                              void* d_out, int out_size) {
    const float* s0 = (const float*)d_in[0];
    const float* s1 = (const float*)d_in[1];
    const float* W0 = (const float*)d_in[2];
    const float* b0 = (const float*)d_in[3];
    const float* W1 = (const float*)d_in[4];
    const float* b1 = (const float*)d_in[5];
    const float* Wf = (const float*)d_in[6];
    const float* bf = (const float*)d_in[7];
    const float* cb = (const float*)d_in[8];
    float* out = (float*)d_out;

    const int H = in_sizes[3];         // 128
    const int E = in_sizes[7];         // 4
    const int K = in_sizes[8] / E;     // 30
    const int D = in_sizes[2] / H;     // 4096
    const int N = in_sizes[0] / D;     // 32768

    const int smem_bytes = (128 + 2 * SBUF) * (int)sizeof(float);  // 70144
    cudaFuncSetAttribute(gemm_vq_mma,
                         cudaFuncAttributeMaxDynamicSharedMemorySize, smem_bytes);

    init_kernel<<<1, 32>>>();
    gemm_vq_mma<<<N / 128, 256, smem_bytes>>>(s0, s1, W0, b0, W1, b1,
                                              Wf, bf, cb, out, N, K);
    repair_kernel<<<MAXFLAG, 128>>>(s0, s1, W0, b0, W1, b1, Wf, bf, cb, out, N, K);
    finalize_kernel<<<1, 32>>>(out, N, K);
}